// round 10
// baseline (speedup 1.0000x reference)
#include <cuda_runtime.h>
#include <cuda_bf16.h>
#include <cuda_fp16.h>
#include <math.h>
#include <stdint.h>

// ---------------------------------------------------------------------------
// Problem constants
// ---------------------------------------------------------------------------
#define BATCH     2
#define NQ        10000
#define MTOT      21760
#define EMBED     256
#define HEADS     8
#define HEAD_DIM  32
#define LEVELS    4
#define POINTS    4
#define COMBOS    (HEADS*LEVELS*POINTS)
#define KDIM      256
#define NQC       384            // combined off(256) + attn(128) output width

__device__ __constant__ int c_shape[LEVELS]  = {128, 64, 32, 16};
__device__ __constant__ int c_start[LEVELS]  = {0, 16384, 20480, 21504};

// ---------------------------------------------------------------------------
// Device scratch
// ---------------------------------------------------------------------------
__device__ __half g_vh[BATCH * MTOT * EMBED];          // projected value, fp16
__device__ float  g_qc[BATCH * NQ * NQC];              // [off(256) | attn(128)]

__device__ __nv_bfloat16 g_val_hi[BATCH * MTOT * KDIM];
__device__ __nv_bfloat16 g_val_lo[BATCH * MTOT * KDIM];
__device__ __nv_bfloat16 g_q_hi[BATCH * NQ * KDIM];
__device__ __nv_bfloat16 g_q_lo[BATCH * NQ * KDIM];
__device__ __nv_bfloat16 g_wv_hi[256 * KDIM],  g_wv_lo[256 * KDIM];
__device__ __nv_bfloat16 g_wq_hi[NQC * KDIM],  g_wq_lo[NQC * KDIM];
__device__ float g_bq[NQC];

// ---------------------------------------------------------------------------
// PTX wrappers
// ---------------------------------------------------------------------------
__device__ __forceinline__ uint32_t smem_u32(const void* p) {
    uint32_t a;
    asm("{ .reg .u64 t; cvta.to.shared.u64 t, %1; cvt.u32.u64 %0, t; }" : "=r"(a) : "l"(p));
    return a;
}
__device__ __forceinline__ void ldsm4(uint32_t* r, uint32_t addr) {
    asm volatile("ldmatrix.sync.aligned.m8n8.x4.shared.b16 {%0,%1,%2,%3}, [%4];"
        : "=r"(r[0]), "=r"(r[1]), "=r"(r[2]), "=r"(r[3]) : "r"(addr));
}
__device__ __forceinline__ void mma_bf16(float* c, const uint32_t* a, const uint32_t* b) {
    asm volatile("mma.sync.aligned.m16n8k16.row.col.f32.bf16.bf16.f32 "
        "{%0,%1,%2,%3}, {%4,%5,%6,%7}, {%8,%9}, {%0,%1,%2,%3};"
        : "+f"(c[0]), "+f"(c[1]), "+f"(c[2]), "+f"(c[3])
        : "r"(a[0]), "r"(a[1]), "r"(a[2]), "r"(a[3]), "r"(b[0]), "r"(b[1]));
}
__device__ __forceinline__ void cpa16(uint32_t dst, const void* src, uint32_t sz) {
    asm volatile("cp.async.ca.shared.global [%0], [%1], 16, %2;" :: "r"(dst), "l"(src), "r"(sz));
}
#define CPA_COMMIT()  asm volatile("cp.async.commit_group;" ::: "memory")
#define CPA_WAIT1()   asm volatile("cp.async.wait_group 1;" ::: "memory")
#define CPA_WAIT0()   asm volatile("cp.async.wait_group 0;" ::: "memory")

// ---------------------------------------------------------------------------
// ONE prep kernel
// ---------------------------------------------------------------------------
__device__ __forceinline__ void split4(const float* in, __nv_bfloat16* hi,
                                       __nv_bfloat16* lo, int i) {
    float4 a = ((const float4*)in)[i];
    __nv_bfloat16 h[4], l[4];
    float v[4] = {a.x, a.y, a.z, a.w};
#pragma unroll
    for (int j = 0; j < 4; j++) {
        h[j] = __float2bfloat16(v[j]);
        l[j] = __float2bfloat16(v[j] - __bfloat162float(h[j]));
    }
    ((uint2*)hi)[i] = *(uint2*)h;
    ((uint2*)lo)[i] = *(uint2*)l;
}

#define NV4 (BATCH * MTOT * KDIM / 4)
#define NQ4 (BATCH * NQ * KDIM / 4)
#define NWV (256 * KDIM)
#define NWQ (NQC * KDIM)
#define PREP_TOT (NV4 + NQ4 + NWV + NWQ + NQC)

__global__ void prep_all(const float* __restrict__ value, const float* __restrict__ query,
                         const float* __restrict__ Wv, const float* __restrict__ Wo,
                         const float* __restrict__ Wa,
                         const float* __restrict__ b_off, const float* __restrict__ b_attn)
{
    int i = blockIdx.x * blockDim.x + threadIdx.x;
    if (i < NV4) { split4(value, g_val_hi, g_val_lo, i); return; }
    i -= NV4;
    if (i < NQ4) { split4(query, g_q_hi, g_q_lo, i); return; }
    i -= NQ4;
    if (i < NWV) {
        int n = i >> 8, k = i & 255;
        float v = Wv[k * 256 + n];
        __nv_bfloat16 h = __float2bfloat16(v);
        g_wv_hi[i] = h;
        g_wv_lo[i] = __float2bfloat16(v - __bfloat162float(h));
        return;
    }
    i -= NWV;
    if (i < NWQ) {
        int n = i >> 8, k = i & 255;
        float v = (n < 256) ? Wo[k * 256 + n] : Wa[k * 128 + (n - 256)];
        __nv_bfloat16 h = __float2bfloat16(v);
        g_wq_hi[i] = h;
        g_wq_lo[i] = __float2bfloat16(v - __bfloat162float(h));
        return;
    }
    i -= NWQ;
    if (i < NQC) g_bq[i] = (i < 256) ? b_off[i] : b_attn[i - 256];
}

// ---------------------------------------------------------------------------
// HMMA GEMM (unchanged from R9)
// ---------------------------------------------------------------------------
#define STG   65536
#define OAL   16384
#define OBH   32768
#define OBL   49152
#define SM_TOTAL (2*STG)

__device__ __forceinline__ uint32_t sw128(int row, int ch) {
    return (uint32_t)row * 128u + (uint32_t)((ch ^ (row & 7)) << 4);
}

__global__ __launch_bounds__(256) void gemm_hmma2(
    const __nv_bfloat16* __restrict__ Ahi, const __nv_bfloat16* __restrict__ Alo,
    const __nv_bfloat16* __restrict__ Bhi, const __nv_bfloat16* __restrict__ Blo,
    const float* __restrict__ bias, float* __restrict__ Cf, __half* __restrict__ Ch,
    int M, int N)
{
    extern __shared__ char smem[];
    const uint32_t sb = smem_u32(smem);
    const int tid  = threadIdx.x;
    const int wid  = tid >> 5;
    const int lane = tid & 31;
    const int wm   = wid & 3;
    const int wn   = wid >> 2;
    const int row0 = blockIdx.y * 128;
    const int col0 = blockIdx.x * 128;

    float acc[2][8][4];
#pragma unroll
    for (int a = 0; a < 2; a++)
#pragma unroll
        for (int b = 0; b < 8; b++)
#pragma unroll
            for (int f = 0; f < 4; f++) acc[a][b][f] = 0.f;

#define LOAD_STAGE(stbase, k0)                                                  \
    do {                                                                        \
        _Pragma("unroll")                                                       \
        for (int i = 0; i < 4; i++) {                                           \
            int c   = tid + i * 256;                                            \
            int row = c >> 3;                                                   \
            int ch  = c & 7;                                                    \
            uint32_t sw = sw128(row, ch);                                       \
            int gr = row0 + row;                                                \
            uint32_t sz = (gr < M) ? 16u : 0u;                                  \
            size_t ga = (size_t)(gr < M ? gr : 0) * 256 + (k0) + ch * 8;        \
            cpa16(sb + (stbase) + sw,        Ahi + ga, sz);                     \
            cpa16(sb + (stbase) + OAL + sw,  Alo + ga, sz);                     \
            size_t gb = (size_t)(col0 + row) * 256 + (k0) + ch * 8;             \
            cpa16(sb + (stbase) + OBH + sw,  Bhi + gb, 16u);                    \
            cpa16(sb + (stbase) + OBL + sw,  Blo + gb, 16u);                    \
        }                                                                       \
    } while (0)

    LOAD_STAGE(0, 0);
    CPA_COMMIT();

#pragma unroll
    for (int cc = 0; cc < 4; cc++) {
        const uint32_t st = (uint32_t)(cc & 1) * STG;
        if (cc < 3) {
            LOAD_STAGE((uint32_t)((cc + 1) & 1) * STG, (cc + 1) * 64);
            CPA_COMMIT();
            CPA_WAIT1();
        } else {
            CPA_WAIT0();
        }
        __syncthreads();

#pragma unroll
        for (int ks = 0; ks < 4; ks++) {
            uint32_t ah[2][4], al[2][4];
#pragma unroll
            for (int tm = 0; tm < 2; tm++) {
                int rA = wm * 32 + tm * 16 + (lane & 15);
                int ch = 2 * ks + (lane >> 4);
                uint32_t ad = sb + st + sw128(rA, ch);
                ldsm4(ah[tm], ad);
                ldsm4(al[tm], ad + OAL);
            }
#pragma unroll
            for (int g = 0; g < 4; g++) {
                int rB  = wn * 64 + g * 16 + ((lane >> 4) & 1) * 8 + (lane & 7);
                int chb = 2 * ks + ((lane >> 3) & 1);
                uint32_t bd = sb + st + OBH + sw128(rB, chb);
                uint32_t bh[4], bl[4];
                ldsm4(bh, bd);
                ldsm4(bl, bd + (OBL - OBH));
#pragma unroll
                for (int tm = 0; tm < 2; tm++) {
                    mma_bf16(acc[tm][2*g],   ah[tm], bh);
                    mma_bf16(acc[tm][2*g],   ah[tm], bl);
                    mma_bf16(acc[tm][2*g],   al[tm], bh);
                    mma_bf16(acc[tm][2*g+1], ah[tm], bh + 2);
                    mma_bf16(acc[tm][2*g+1], ah[tm], bl + 2);
                    mma_bf16(acc[tm][2*g+1], al[tm], bh + 2);
                }
            }
        }
        __syncthreads();
    }

    const int row_in = lane >> 2;
    const int col_in = 2 * (lane & 3);
#pragma unroll
    for (int tm = 0; tm < 2; tm++) {
        const int gr0 = row0 + wm * 32 + tm * 16 + row_in;
#pragma unroll
        for (int j = 0; j < 8; j++) {
            const int gcol = col0 + wn * 64 + j * 8 + col_in;
            const float bx = bias[gcol];
            const float by = bias[gcol + 1];
            if (Ch) {
                if (gr0 < M)
                    *(__half2*)&Ch[(size_t)gr0 * N + gcol] =
                        __floats2half2_rn(acc[tm][j][0] + bx, acc[tm][j][1] + by);
                if (gr0 + 8 < M)
                    *(__half2*)&Ch[(size_t)(gr0 + 8) * N + gcol] =
                        __floats2half2_rn(acc[tm][j][2] + bx, acc[tm][j][3] + by);
            } else {
                if (gr0 < M)
                    *(float2*)&Cf[(size_t)gr0 * N + gcol] =
                        make_float2(acc[tm][j][0] + bx, acc[tm][j][1] + by);
                if (gr0 + 8 < M)
                    *(float2*)&Cf[(size_t)(gr0 + 8) * N + gcol] =
                        make_float2(acc[tm][j][2] + bx, acc[tm][j][3] + by);
            }
        }
    }
#undef LOAD_STAGE
}

// ---------------------------------------------------------------------------
// Sampler v3: half2 lanes + corner pairing.
// Phase 2: lane carries 2 channels (half2). Lanes 0-15 do corners (0,1),
// lanes 16-31 do corners (2,3) of the SAME combo -> 2 LDG per combo (was 4).
// Cross-half combine via shfl_xor(16); lanes 0-15 store float2.
// ---------------------------------------------------------------------------
#define QPB 2

__global__ __launch_bounds__(256) void deform_sample(
    const float* __restrict__ ref_points, float* __restrict__ out)
{
    __shared__ float4 s_w[QPB * COMBOS];
    __shared__ int4   s_i[QPB * COMBOS];

    const int t = threadIdx.x;

    // ---------------- Phase 1 (unchanged) ----------------
    {
        const int q    = t >> 7;
        const int c    = t & 127;
        const int head = c >> 4;
        const int i16  = c & 15;
        const int lv   = i16 >> 2;
        const int bn   = blockIdx.x * QPB + q;
        const int b    = bn / NQ;

        float lg = g_qc[(size_t)bn * NQC + 256 + c];
        float mx = lg;
#pragma unroll
        for (int s = 8; s >= 1; s >>= 1)
            mx = fmaxf(mx, __shfl_xor_sync(0xffffffffu, mx, s));
        float e = __expf(lg - mx);
        float ssum = e;
#pragma unroll
        for (int s = 8; s >= 1; s >>= 1)
            ssum += __shfl_xor_sync(0xffffffffu, ssum, s);
        const float aw = e / ssum;

        const float2 od = *(const float2*)&g_qc[(size_t)bn * NQC + 2 * c];
        const float rx = ref_points[bn * 2 + 0];
        const float ry = ref_points[bn * 2 + 1];

        const int   S  = c_shape[lv];
        const float fS = (float)S;
        const float x = (rx + od.x / fS) * fS - 0.5f;
        const float y = (ry + od.y / fS) * fS - 0.5f;
        const float x0f = floorf(x), y0f = floorf(y);
        const float lx = x - x0f, ly = y - y0f;
        const int x0 = (int)x0f, y0 = (int)y0f;
        const int x1 = x0 + 1,   y1 = y0 + 1;

        const bool vx0 = ((unsigned)x0 < (unsigned)S);
        const bool vx1 = ((unsigned)x1 < (unsigned)S);
        const bool vy0 = ((unsigned)y0 < (unsigned)S);
        const bool vy1 = ((unsigned)y1 < (unsigned)S);

        const int xc0 = min(max(x0, 0), S - 1);
        const int xc1 = min(max(x1, 0), S - 1);
        const int yc0 = min(max(y0, 0), S - 1);
        const int yc1 = min(max(y1, 0), S - 1);

        float4 wv;
        wv.x = (vx0 && vy0) ? (1.f - lx) * (1.f - ly) * aw : 0.f;
        wv.y = (vx1 && vy0) ? lx * (1.f - ly) * aw : 0.f;
        wv.z = (vx0 && vy1) ? (1.f - lx) * ly * aw : 0.f;
        wv.w = (vx1 && vy1) ? lx * ly * aw : 0.f;

        const int base = b * MTOT + c_start[lv];
        const int hoff = head * HEAD_DIM;
        int4 iv;
        iv.x = (base + yc0 * S + xc0) * EMBED + hoff;
        iv.y = (base + yc0 * S + xc1) * EMBED + hoff;
        iv.z = (base + yc1 * S + xc0) * EMBED + hoff;
        iv.w = (base + yc1 * S + xc1) * EMBED + hoff;

        s_w[t] = wv;
        s_i[t] = iv;
    }
    __syncthreads();

    // ---------------- Phase 2: half2 lanes, corner-paired ----------------
    const int head = t >> 5;
    const int lane = t & 31;
    const int hi16 = lane >> 4;          // 0 -> corners (0,1); 1 -> corners (2,3)
    const int lch  = (lane & 15) * 2;    // channel pair base

#pragma unroll
    for (int q = 0; q < QPB; q++) {
        const int bn   = blockIdx.x * QPB + q;
        const int slot = q * COMBOS + head * (LEVELS * POINTS);

        float ax = 0.f, ay = 0.f;
#pragma unroll
        for (int i = 0; i < LEVELS * POINTS; i++) {
            const float4 wv = s_w[slot + i];
            const int4   iv = s_i[slot + i];
            const int   i0 = hi16 ? iv.z : iv.x;
            const int   i1 = hi16 ? iv.w : iv.y;
            const float w0 = hi16 ? wv.z : wv.x;
            const float w1 = hi16 ? wv.w : wv.y;
            const float2 f0 = __half22float2(__ldg((const __half2*)&g_vh[i0 + lch]));
            const float2 f1 = __half22float2(__ldg((const __half2*)&g_vh[i1 + lch]));
            ax = fmaf(w0, f0.x, ax);
            ay = fmaf(w0, f0.y, ay);
            ax = fmaf(w1, f1.x, ax);
            ay = fmaf(w1, f1.y, ay);
        }
        ax += __shfl_xor_sync(0xffffffffu, ax, 16);
        ay += __shfl_xor_sync(0xffffffffu, ay, 16);
        if (lane < 16)
            *(float2*)&out[(size_t)bn * EMBED + head * HEAD_DIM + lch] =
                make_float2(ax, ay);
    }
}

// ---------------------------------------------------------------------------
// Launch: 4 kernels total
// ---------------------------------------------------------------------------
extern "C" void kernel_launch(void* const* d_in, const int* in_sizes, int n_in,
                              void* d_out, int out_size)
{
    const float* query  = (const float*)d_in[0];
    const float* value  = (const float*)d_in[2];
    const float* refpts = (const float*)d_in[3];
    const float* W_off  = (const float*)d_in[6];
    const float* b_off  = (const float*)d_in[7];
    const float* W_attn = (const float*)d_in[8];
    const float* b_attn = (const float*)d_in[9];
    const float* W_v    = (const float*)d_in[10];
    const float* b_v    = (const float*)d_in[11];
    float* out = (float*)d_out;

    void *pvh16, *pqc, *pbq;
    void *pvh, *pvl, *pqh, *pql, *pwvh, *pwvl, *pwqh, *pwql;
    cudaGetSymbolAddress(&pvh16, g_vh);
    cudaGetSymbolAddress(&pqc,   g_qc);
    cudaGetSymbolAddress(&pbq,   g_bq);
    cudaGetSymbolAddress(&pvh, g_val_hi);  cudaGetSymbolAddress(&pvl, g_val_lo);
    cudaGetSymbolAddress(&pqh, g_q_hi);    cudaGetSymbolAddress(&pql, g_q_lo);
    cudaGetSymbolAddress(&pwvh, g_wv_hi);  cudaGetSymbolAddress(&pwvl, g_wv_lo);
    cudaGetSymbolAddress(&pwqh, g_wq_hi);  cudaGetSymbolAddress(&pwql, g_wq_lo);

    const int MV = BATCH * MTOT;   // 43520
    const int MQ = BATCH * NQ;     // 20000

    cudaFuncSetAttribute(gemm_hmma2, cudaFuncAttributeMaxDynamicSharedMemorySize, SM_TOTAL);

    prep_all<<<(PREP_TOT + 255) / 256, 256>>>(value, query, W_v, W_off, W_attn,
                                              b_off, b_attn);

    {
        dim3 grid(2, (MV + 127) / 128);   // N=256 -> fp16 g_vh
        gemm_hmma2<<<grid, 256, SM_TOTAL>>>((const __nv_bfloat16*)pvh, (const __nv_bfloat16*)pvl,
                                            (const __nv_bfloat16*)pwvh, (const __nv_bfloat16*)pwvl,
                                            b_v, nullptr, (__half*)pvh16, MV, 256);
    }
    {
        dim3 grid(3, (MQ + 127) / 128);   // N=384 -> fp32 g_qc
        gemm_hmma2<<<grid, 256, SM_TOTAL>>>((const __nv_bfloat16*)pqh, (const __nv_bfloat16*)pql,
                                            (const __nv_bfloat16*)pwqh, (const __nv_bfloat16*)pwql,
                                            (const float*)pbq, (float*)pqc, nullptr, MQ, NQC);
    }
    deform_sample<<<(BATCH * NQ) / QPB, 256>>>(refpts, out);
}

// round 11
// speedup vs baseline: 1.2104x; 1.2104x over previous
#include <cuda_runtime.h>
#include <cuda_bf16.h>
#include <cuda_fp16.h>
#include <math.h>
#include <stdint.h>

// ---------------------------------------------------------------------------
// Problem constants
// ---------------------------------------------------------------------------
#define BATCH     2
#define NQ        10000
#define MTOT      21760
#define EMBED     256
#define HEADS     8
#define HEAD_DIM  32
#define LEVELS    4
#define POINTS    4
#define COMBOS    (HEADS*LEVELS*POINTS)
#define KDIM      256
#define NQC       384            // combined off(256) + attn(128) width

#define MV (BATCH * MTOT)        // 43520
#define MQ (BATCH * NQ)          // 20000
#define GRID_V 680               // 2 x 340
#define GRID_Q 471               // 3 x 157

__device__ __constant__ int c_shape[LEVELS]  = {128, 64, 32, 16};
__device__ __constant__ int c_start[LEVELS]  = {0, 16384, 20480, 21504};

// ---------------------------------------------------------------------------
// Device scratch
// ---------------------------------------------------------------------------
__device__ __half g_vh[BATCH * MTOT * EMBED];          // projected value, fp16
__device__ float  g_qc[BATCH * NQ * NQC];              // [off(256) | attn(128)]

__device__ __nv_bfloat16 g_wv_hi[256 * KDIM],  g_wv_lo[256 * KDIM];
__device__ __nv_bfloat16 g_wq_hi[NQC * KDIM],  g_wq_lo[NQC * KDIM];
__device__ float g_bq[NQC];

// ---------------------------------------------------------------------------
// PTX wrappers
// ---------------------------------------------------------------------------
__device__ __forceinline__ uint32_t smem_u32(const void* p) {
    uint32_t a;
    asm("{ .reg .u64 t; cvta.to.shared.u64 t, %1; cvt.u32.u64 %0, t; }" : "=r"(a) : "l"(p));
    return a;
}
__device__ __forceinline__ void ldsm4(uint32_t* r, uint32_t addr) {
    asm volatile("ldmatrix.sync.aligned.m8n8.x4.shared.b16 {%0,%1,%2,%3}, [%4];"
        : "=r"(r[0]), "=r"(r[1]), "=r"(r[2]), "=r"(r[3]) : "r"(addr));
}
__device__ __forceinline__ void mma_bf16(float* c, const uint32_t* a, const uint32_t* b) {
    asm volatile("mma.sync.aligned.m16n8k16.row.col.f32.bf16.bf16.f32 "
        "{%0,%1,%2,%3}, {%4,%5,%6,%7}, {%8,%9}, {%0,%1,%2,%3};"
        : "+f"(c[0]), "+f"(c[1]), "+f"(c[2]), "+f"(c[3])
        : "r"(a[0]), "r"(a[1]), "r"(a[2]), "r"(a[3]), "r"(b[0]), "r"(b[1]));
}
__device__ __forceinline__ void cpa16(uint32_t dst, const void* src, uint32_t sz) {
    asm volatile("cp.async.ca.shared.global [%0], [%1], 16, %2;" :: "r"(dst), "l"(src), "r"(sz));
}
#define CPA_COMMIT()  asm volatile("cp.async.commit_group;" ::: "memory")
#define CPA_WAIT1()   asm volatile("cp.async.wait_group 1;" ::: "memory")
#define CPA_WAIT0()   asm volatile("cp.async.wait_group 0;" ::: "memory")

// ---------------------------------------------------------------------------
// Prep (weights only now): transpose+split Wv, [Wo|Wa], bias concat
// ---------------------------------------------------------------------------
#define NWV (256 * KDIM)
#define NWQ (NQC * KDIM)
#define PREPW_TOT (NWV + NWQ + NQC)

__global__ void prep_weights(const float* __restrict__ Wv, const float* __restrict__ Wo,
                             const float* __restrict__ Wa,
                             const float* __restrict__ b_off, const float* __restrict__ b_attn)
{
    int i = blockIdx.x * blockDim.x + threadIdx.x;
    if (i < NWV) {
        int n = i >> 8, k = i & 255;
        float v = Wv[k * 256 + n];
        __nv_bfloat16 h = __float2bfloat16(v);
        g_wv_hi[i] = h;
        g_wv_lo[i] = __float2bfloat16(v - __bfloat162float(h));
        return;
    }
    i -= NWV;
    if (i < NWQ) {
        int n = i >> 8, k = i & 255;
        float v = (n < 256) ? Wo[k * 256 + n] : Wa[k * 128 + (n - 256)];
        __nv_bfloat16 h = __float2bfloat16(v);
        g_wq_hi[i] = h;
        g_wq_lo[i] = __float2bfloat16(v - __bfloat162float(h));
        return;
    }
    i -= NWQ;
    if (i < NQC) g_bq[i] = (i < 256) ? b_off[i] : b_attn[i - 256];
}

// ---------------------------------------------------------------------------
// Fused HMMA GEMM with in-kernel fp32->bf16 hi/lo split of A.
// One launch covers both GEMMs:
//   bid <  680: g_vh(fp16) = value[MV,256] @ Wv^T + b_v    (N=256)
//   bid >= 680: g_qc(fp32) = query[MQ,256] @ Wq^T + bq     (N=384)
// CTA tile 128x128, BK=64, double-buffered. 256 thr (8 warps, 4m x 2n).
// Stage (96KB): [A fp32 32K][A_hi 16K][A_lo 16K][B_hi 16K][B_lo 16K]
// ---------------------------------------------------------------------------
#define OAF   0
#define OAH   32768
#define OAL   49152
#define OBH   65536
#define OBL   81920
#define STG   98304
#define SM_TOTAL (2*STG)         // 192 KB

__device__ __forceinline__ uint32_t sw128(int row, int ch) {   // bf16 tile: 8 x 16B chunks/row
    return (uint32_t)row * 128u + (uint32_t)((ch ^ (row & 7)) << 4);
}

__global__ __launch_bounds__(256) void gemm_fused(
    const float* __restrict__ Aval, const float* __restrict__ Aq,
    const float* __restrict__ b_v)
{
    extern __shared__ char smem[];
    const uint32_t sb = smem_u32(smem);
    const int tid  = threadIdx.x;
    const int wid  = tid >> 5;
    const int lane = tid & 31;
    const int wm   = wid & 3;
    const int wn   = wid >> 2;

    // ---- job decode ----
    const float* Af;
    const __nv_bfloat16 *Bh, *Bl;
    const float* bias;
    __half* Ch = nullptr;
    float*  Cf = nullptr;
    int M, N, cx, cy;
    if (blockIdx.x < GRID_V) {
        cx = blockIdx.x & 1;  cy = blockIdx.x >> 1;
        Af = Aval; Bh = g_wv_hi; Bl = g_wv_lo; bias = b_v;
        Ch = g_vh; M = MV; N = 256;
    } else {
        int b2 = blockIdx.x - GRID_V;
        cx = b2 % 3;  cy = b2 / 3;
        Af = Aq; Bh = g_wq_hi; Bl = g_wq_lo; bias = g_bq;
        Cf = g_qc; M = MQ; N = NQC;
    }
    const int row0 = cy * 128;
    const int col0 = cx * 128;

    float acc[2][8][4];
#pragma unroll
    for (int a = 0; a < 2; a++)
#pragma unroll
        for (int b = 0; b < 8; b++)
#pragma unroll
            for (int f = 0; f < 4; f++) acc[a][b][f] = 0.f;

    // A fp32 stage: 128 rows x 64 K x 4B = 2048 16B-chunks, linear layout.
    // B bf16 stage: 128 rows x 64 K x 2B, sw128 layout, 1024 chunks each (hi/lo).
#define LOAD_STAGE(stbase, k0)                                                  \
    do {                                                                        \
        _Pragma("unroll")                                                       \
        for (int i = 0; i < 8; i++) {                                           \
            int c   = tid + i * 256;       /* 0..2047 */                        \
            int row = c >> 4;                                                   \
            int ch  = c & 15;                                                   \
            int gr  = row0 + row;                                               \
            uint32_t sz = (gr < M) ? 16u : 0u;                                  \
            const float* src = Af + (size_t)(gr < M ? gr : 0) * KDIM + (k0) + ch * 4; \
            cpa16(sb + (stbase) + OAF + ((uint32_t)c << 4), src, sz);           \
        }                                                                       \
        _Pragma("unroll")                                                       \
        for (int i = 0; i < 4; i++) {                                           \
            int c   = tid + i * 256;       /* 0..1023 */                        \
            int row = c >> 3;                                                   \
            int ch  = c & 7;                                                    \
            uint32_t sw = sw128(row, ch);                                       \
            size_t gb = (size_t)(col0 + row) * KDIM + (k0) + ch * 8;            \
            cpa16(sb + (stbase) + OBH + sw, Bh + gb, 16u);                      \
            cpa16(sb + (stbase) + OBL + sw, Bl + gb, 16u);                      \
        }                                                                       \
    } while (0)

    LOAD_STAGE(0, 0);
    CPA_COMMIT();

#pragma unroll
    for (int cc = 0; cc < 4; cc++) {
        const uint32_t st = (uint32_t)(cc & 1) * STG;
        if (cc < 3) {
            LOAD_STAGE((uint32_t)((cc + 1) & 1) * STG, (cc + 1) * 64);
            CPA_COMMIT();
            CPA_WAIT1();
        } else {
            CPA_WAIT0();
        }
        __syncthreads();

        // ---- convert A fp32 -> bf16 hi/lo (this stage) ----
#pragma unroll
        for (int i = 0; i < 8; i++) {
            int c   = tid + i * 256;
            int row = c >> 4;
            int ch  = c & 15;
            float4 f = *(const float4*)(smem + st + OAF + ((uint32_t)c << 4));
            __nv_bfloat16 h4[4], l4[4];
            float v[4] = {f.x, f.y, f.z, f.w};
#pragma unroll
            for (int j = 0; j < 4; j++) {
                h4[j] = __float2bfloat16(v[j]);
                l4[j] = __float2bfloat16(v[j] - __bfloat162float(h4[j]));
            }
            uint32_t dsto = sw128(row, ch >> 1) + (uint32_t)(ch & 1) * 8;
            *(uint2*)(smem + st + OAH + dsto) = *(uint2*)h4;
            *(uint2*)(smem + st + OAL + dsto) = *(uint2*)l4;
        }
        __syncthreads();

        // ---- MMA: 4 k16-steps ----
#pragma unroll
        for (int ks = 0; ks < 4; ks++) {
            uint32_t ah[2][4], al[2][4];
#pragma unroll
            for (int tm = 0; tm < 2; tm++) {
                int rA = wm * 32 + tm * 16 + (lane & 15);
                int ch = 2 * ks + (lane >> 4);
                uint32_t ad = sb + st + OAH + sw128(rA, ch);
                ldsm4(ah[tm], ad);
                ldsm4(al[tm], ad + (OAL - OAH));
            }
#pragma unroll
            for (int g = 0; g < 4; g++) {
                int rB  = wn * 64 + g * 16 + ((lane >> 4) & 1) * 8 + (lane & 7);
                int chb = 2 * ks + ((lane >> 3) & 1);
                uint32_t bd = sb + st + OBH + sw128(rB, chb);
                uint32_t bh[4], bl[4];
                ldsm4(bh, bd);
                ldsm4(bl, bd + (OBL - OBH));
#pragma unroll
                for (int tm = 0; tm < 2; tm++) {
                    mma_bf16(acc[tm][2*g],   ah[tm], bh);
                    mma_bf16(acc[tm][2*g],   ah[tm], bl);
                    mma_bf16(acc[tm][2*g],   al[tm], bh);
                    mma_bf16(acc[tm][2*g+1], ah[tm], bh + 2);
                    mma_bf16(acc[tm][2*g+1], ah[tm], bl + 2);
                    mma_bf16(acc[tm][2*g+1], al[tm], bh + 2);
                }
            }
        }
        __syncthreads();
    }

    // ---- epilogue ----
    const int row_in = lane >> 2;
    const int col_in = 2 * (lane & 3);
#pragma unroll
    for (int tm = 0; tm < 2; tm++) {
        const int gr0 = row0 + wm * 32 + tm * 16 + row_in;
#pragma unroll
        for (int j = 0; j < 8; j++) {
            const int gcol = col0 + wn * 64 + j * 8 + col_in;
            const float bx = bias[gcol];
            const float by = bias[gcol + 1];
            if (Ch) {
                if (gr0 < M)
                    *(__half2*)&Ch[(size_t)gr0 * N + gcol] =
                        __floats2half2_rn(acc[tm][j][0] + bx, acc[tm][j][1] + by);
                if (gr0 + 8 < M)
                    *(__half2*)&Ch[(size_t)(gr0 + 8) * N + gcol] =
                        __floats2half2_rn(acc[tm][j][2] + bx, acc[tm][j][3] + by);
            } else {
                if (gr0 < M)
                    *(float2*)&Cf[(size_t)gr0 * N + gcol] =
                        make_float2(acc[tm][j][0] + bx, acc[tm][j][1] + by);
                if (gr0 + 8 < M)
                    *(float2*)&Cf[(size_t)(gr0 + 8) * N + gcol] =
                        make_float2(acc[tm][j][2] + bx, acc[tm][j][3] + by);
            }
        }
    }
#undef LOAD_STAGE
}

// ---------------------------------------------------------------------------
// Sampler: exact R9 form (best measured: 93.4us; one line per LDG)
// ---------------------------------------------------------------------------
#define QPB 2

__global__ __launch_bounds__(256) void deform_sample(
    const float* __restrict__ ref_points, float* __restrict__ out)
{
    __shared__ float4 s_w[QPB * COMBOS];
    __shared__ int4   s_i[QPB * COMBOS];

    const int t = threadIdx.x;
    {
        const int q    = t >> 7;
        const int c    = t & 127;
        const int head = c >> 4;
        const int i16  = c & 15;
        const int lv   = i16 >> 2;
        const int bn   = blockIdx.x * QPB + q;
        const int b    = bn / NQ;

        float lg = g_qc[(size_t)bn * NQC + 256 + c];
        float mx = lg;
#pragma unroll
        for (int s = 8; s >= 1; s >>= 1)
            mx = fmaxf(mx, __shfl_xor_sync(0xffffffffu, mx, s));
        float e = __expf(lg - mx);
        float ssum = e;
#pragma unroll
        for (int s = 8; s >= 1; s >>= 1)
            ssum += __shfl_xor_sync(0xffffffffu, ssum, s);
        const float aw = e / ssum;

        const float2 od = *(const float2*)&g_qc[(size_t)bn * NQC + 2 * c];
        const float rx = ref_points[bn * 2 + 0];
        const float ry = ref_points[bn * 2 + 1];

        const int   S  = c_shape[lv];
        const float fS = (float)S;
        const float x = (rx + od.x / fS) * fS - 0.5f;
        const float y = (ry + od.y / fS) * fS - 0.5f;
        const float x0f = floorf(x), y0f = floorf(y);
        const float lx = x - x0f, ly = y - y0f;
        const int x0 = (int)x0f, y0 = (int)y0f;
        const int x1 = x0 + 1,   y1 = y0 + 1;

        const bool vx0 = ((unsigned)x0 < (unsigned)S);
        const bool vx1 = ((unsigned)x1 < (unsigned)S);
        const bool vy0 = ((unsigned)y0 < (unsigned)S);
        const bool vy1 = ((unsigned)y1 < (unsigned)S);

        const int xc0 = min(max(x0, 0), S - 1);
        const int xc1 = min(max(x1, 0), S - 1);
        const int yc0 = min(max(y0, 0), S - 1);
        const int yc1 = min(max(y1, 0), S - 1);

        float4 wv;
        wv.x = (vx0 && vy0) ? (1.f - lx) * (1.f - ly) * aw : 0.f;
        wv.y = (vx1 && vy0) ? lx * (1.f - ly) * aw : 0.f;
        wv.z = (vx0 && vy1) ? (1.f - lx) * ly * aw : 0.f;
        wv.w = (vx1 && vy1) ? lx * ly * aw : 0.f;

        const int base = b * MTOT + c_start[lv];
        const int hoff = head * HEAD_DIM;
        int4 iv;
        iv.x = (base + yc0 * S + xc0) * EMBED + hoff;
        iv.y = (base + yc0 * S + xc1) * EMBED + hoff;
        iv.z = (base + yc1 * S + xc0) * EMBED + hoff;
        iv.w = (base + yc1 * S + xc1) * EMBED + hoff;

        s_w[t] = wv;
        s_i[t] = iv;
    }
    __syncthreads();

    const int head = t >> 5;
    const int lane = t & 31;
#pragma unroll
    for (int q = 0; q < QPB; q++) {
        const int bn   = blockIdx.x * QPB + q;
        const int slot = q * COMBOS + head * (LEVELS * POINTS);
        float acc = 0.0f;
#pragma unroll
        for (int i = 0; i < LEVELS * POINTS; i++) {
            const float4 wv = s_w[slot + i];
            const int4   iv = s_i[slot + i];
            float v0 = __half2float(__ldg(&g_vh[iv.x + lane]));
            float v1 = __half2float(__ldg(&g_vh[iv.y + lane]));
            float v2 = __half2float(__ldg(&g_vh[iv.z + lane]));
            float v3 = __half2float(__ldg(&g_vh[iv.w + lane]));
            acc = fmaf(wv.x, v0, acc);
            acc = fmaf(wv.y, v1, acc);
            acc = fmaf(wv.z, v2, acc);
            acc = fmaf(wv.w, v3, acc);
        }
        out[(size_t)bn * EMBED + head * HEAD_DIM + lane] = acc;
    }
}

// ---------------------------------------------------------------------------
// Launch: 3 kernels total
// ---------------------------------------------------------------------------
extern "C" void kernel_launch(void* const* d_in, const int* in_sizes, int n_in,
                              void* d_out, int out_size)
{
    const float* query  = (const float*)d_in[0];
    const float* value  = (const float*)d_in[2];
    const float* refpts = (const float*)d_in[3];
    const float* W_off  = (const float*)d_in[6];
    const float* b_off  = (const float*)d_in[7];
    const float* W_attn = (const float*)d_in[8];
    const float* b_attn = (const float*)d_in[9];
    const float* W_v    = (const float*)d_in[10];
    const float* b_v    = (const float*)d_in[11];
    float* out = (float*)d_out;

    cudaFuncSetAttribute(gemm_fused, cudaFuncAttributeMaxDynamicSharedMemorySize, SM_TOTAL);

    // 1) weight prep (small)
    prep_weights<<<(PREPW_TOT + 255) / 256, 256>>>(W_v, W_off, W_attn, b_off, b_attn);

    // 2) both GEMMs, one launch, fp32 A split in-kernel
    gemm_fused<<<GRID_V + GRID_Q, 256, SM_TOTAL>>>(value, query, b_v);

    // 3) sampler
    deform_sample<<<(BATCH * NQ) / QPB, 256>>>(refpts, out);
}